// round 15
// baseline (speedup 1.0000x reference)
#include <cuda_runtime.h>
#include <math.h>

#define NBLK 512
#define BS   256
#define CS   128                    // tokens per CTA chunk
#define KHN  8
#define DH   128
#define BN   32
#define HN   32
#define MBN  16
#define NCH  32                     // max chunks per sequence (4096/128)
#define REP  4
#define QK_SCALE 0.08838834764831845f

// Split-KV partial results: per (b, kv_head, chunk, rep_head)
__device__ float  g_part_acc[BN * KHN * NCH * REP * DH];   // 16 MB
__device__ float2 g_part_ml [BN * KHN * NCH * REP];        // 256 KB
// Completion counters per (b, kv_head). Zero-initialized; the last CTA resets
// its counter to 0 after combining, so state is identical across replays.
__device__ int    g_done    [BN * KHN];

__global__ void __launch_bounds__(128, 10)
attn_partial_kernel(const float* __restrict__ q,
                    const float* __restrict__ knew,
                    const float* __restrict__ vnew,
                    const float* __restrict__ kc,
                    const float* __restrict__ vc,
                    const int*   __restrict__ bt,
                    const int*   __restrict__ cl,
                    float*       __restrict__ out)
{
    const int c = blockIdx.x;   // 128-token chunk index within sequence
    const int g = blockIdx.y;   // kv head
    const int b = blockIdx.z;   // sequence

    const int len   = cl[b];
    const int start = c * CS;
    if (start >= len) return;                    // inactive chunk
    const int n    = min(CS, len - start);       // valid tokens in this chunk
    const int nc   = (len + CS - 1) >> 7;        // active chunks for this (b,g)
    const int last = len - 1;
    const int tsub = (last >= start && last < start + CS) ? (last - start) : -1;
    // cache block + 128-token half within it
    const int blk  = bt[b * MBN + (c >> 1)];
    const int hoff = (c & 1) * CS;               // token offset inside cache block

    __shared__ float qs[REP * DH];       // 2 KB: 4 query heads
    __shared__ float sc[REP][CS];        // 2 KB: scores -> probabilities
    __shared__ float red[4 * REP * DH];  // 8 KB: per-warp V partials
    __shared__ int   s_last;

    const int tid = threadIdx.x;

    // ---- load Q (heads g*4 .. g*4+3 are contiguous in q) ----
    {
        const size_t qoff = (size_t)b * HN * DH + (size_t)g * REP * DH;
        qs[tid]       = q[qoff + tid];
        qs[tid + 128] = q[qoff + tid + 128];
        qs[tid + 256] = q[qoff + tid + 256];
        qs[tid + 384] = q[qoff + tid + 384];
    }
    __syncthreads();

    const int w    = tid >> 5;     // 0..3
    const int lane = tid & 31;
    const int sub  = lane & 7;     // 8 lanes cooperate per token row
    const int grp  = lane >> 3;    // 4 tokens in flight per warp pass

    const size_t rowstride = (size_t)KHN * DH;   // floats between tokens
    const float* kbase = kc + (((size_t)blk * BS + hoff) * KHN + (size_t)g) * DH;
    const float* knrow = knew + (size_t)(b * KHN + g) * DH;
    const float4* q4   = (const float4*)qs;

    // ---- phase 1: scores = (Q . K) * scale ----
    // Lane group of 8 reads CONTIGUOUS 128B per j-step: kr[j*8 + sub].
    #pragma unroll 2
    for (int p = 0; p < 8; ++p) {
        const int t = w * 32 + p * 4 + grp;       // 0..127, all covered
        float s0 = 0.f, s1 = 0.f, s2 = 0.f, s3 = 0.f;
        if (t < n) {
            const float4* kr = (const float4*)((t == tsub)
                                 ? knrow
                                 : (kbase + (size_t)t * rowstride));
            #pragma unroll
            for (int j = 0; j < 4; ++j) {
                const float4 kv = kr[j * 8 + sub];
                float4 qa;
                qa = q4[      j * 8 + sub];
                s0 += kv.x*qa.x + kv.y*qa.y + kv.z*qa.z + kv.w*qa.w;
                qa = q4[32  + j * 8 + sub];
                s1 += kv.x*qa.x + kv.y*qa.y + kv.z*qa.z + kv.w*qa.w;
                qa = q4[64  + j * 8 + sub];
                s2 += kv.x*qa.x + kv.y*qa.y + kv.z*qa.z + kv.w*qa.w;
                qa = q4[96  + j * 8 + sub];
                s3 += kv.x*qa.x + kv.y*qa.y + kv.z*qa.z + kv.w*qa.w;
            }
        }
        #pragma unroll
        for (int m = 4; m > 0; m >>= 1) {
            s0 += __shfl_xor_sync(0xffffffffu, s0, m);
            s1 += __shfl_xor_sync(0xffffffffu, s1, m);
            s2 += __shfl_xor_sync(0xffffffffu, s2, m);
            s3 += __shfl_xor_sync(0xffffffffu, s3, m);
        }
        if (sub < 4) {
            const float val = (sub == 0) ? s0 : (sub == 1) ? s1 : (sub == 2) ? s2 : s3;
            sc[sub][t] = (t < n) ? val * QK_SCALE : -INFINITY;
        }
    }
    __syncthreads();

    // ---- phase 2: per-head chunk softmax (unnormalized), warp r handles head r ----
    const int mlbase = ((b * KHN + g) * NCH + c) * REP;
    {
        float vv[4];
        float m = -INFINITY;
        #pragma unroll
        for (int j = 0; j < 4; ++j) {
            vv[j] = sc[w][lane + 32 * j];
            m = fmaxf(m, vv[j]);
        }
        #pragma unroll
        for (int s = 16; s > 0; s >>= 1)
            m = fmaxf(m, __shfl_xor_sync(0xffffffffu, m, s));
        float l = 0.f;
        #pragma unroll
        for (int j = 0; j < 4; ++j) {
            const float e = __expf(vv[j] - m);   // exp(-inf)=0 for masked slots
            l += e;
            sc[w][lane + 32 * j] = e;
        }
        #pragma unroll
        for (int s = 16; s > 0; s >>= 1)
            l += __shfl_xor_sync(0xffffffffu, l, s);
        if (lane == 0)
            g_part_ml[mlbase + w] = make_float2(m, l);
    }
    __syncthreads();

    // ---- phase 3: acc = P . V  (warp per token row; lane owns float4 of dims) ----
    // Reads the CACHE row for every token; the new token's contribution is
    // fixed up once after the loop: acc += p[tsub] * (v_new - v_stale).
    {
        const int lo = lane * 4;   // float offset within the 128-dim row
        const float* vrow0 = vc + (((size_t)blk * BS + hoff) * KHN + (size_t)g) * DH + lo;

        float4 a0 = make_float4(0.f, 0.f, 0.f, 0.f);
        float4 a1 = a0, a2 = a0, a3 = a0;

        #pragma unroll 4
        for (int t = w; t < n; t += 4) {
            const float4 vv = *(const float4*)(vrow0 + (size_t)t * rowstride);
            const float p0 = sc[0][t];
            const float p1 = sc[1][t];
            const float p2 = sc[2][t];
            const float p3 = sc[3][t];
            a0.x = fmaf(p0, vv.x, a0.x); a0.y = fmaf(p0, vv.y, a0.y);
            a0.z = fmaf(p0, vv.z, a0.z); a0.w = fmaf(p0, vv.w, a0.w);
            a1.x = fmaf(p1, vv.x, a1.x); a1.y = fmaf(p1, vv.y, a1.y);
            a1.z = fmaf(p1, vv.z, a1.z); a1.w = fmaf(p1, vv.w, a1.w);
            a2.x = fmaf(p2, vv.x, a2.x); a2.y = fmaf(p2, vv.y, a2.y);
            a2.z = fmaf(p2, vv.z, a2.z); a2.w = fmaf(p2, vv.w, a2.w);
            a3.x = fmaf(p3, vv.x, a3.x); a3.y = fmaf(p3, vv.y, a3.y);
            a3.z = fmaf(p3, vv.z, a3.z); a3.w = fmaf(p3, vv.w, a3.w);
        }

        if (tsub >= 0 && (tsub & 3) == w) {
            const float4 vst = *(const float4*)(vrow0 + (size_t)tsub * rowstride);
            const float4 vn4 = *(const float4*)(vnew + (size_t)(b * KHN + g) * DH + lo);
            const float dx = vn4.x - vst.x, dy = vn4.y - vst.y;
            const float dz = vn4.z - vst.z, dw = vn4.w - vst.w;
            const float p0 = sc[0][tsub], p1 = sc[1][tsub];
            const float p2 = sc[2][tsub], p3 = sc[3][tsub];
            a0.x = fmaf(p0, dx, a0.x); a0.y = fmaf(p0, dy, a0.y);
            a0.z = fmaf(p0, dz, a0.z); a0.w = fmaf(p0, dw, a0.w);
            a1.x = fmaf(p1, dx, a1.x); a1.y = fmaf(p1, dy, a1.y);
            a1.z = fmaf(p1, dz, a1.z); a1.w = fmaf(p1, dw, a1.w);
            a2.x = fmaf(p2, dx, a2.x); a2.y = fmaf(p2, dy, a2.y);
            a2.z = fmaf(p2, dz, a2.z); a2.w = fmaf(p2, dw, a2.w);
            a3.x = fmaf(p3, dx, a3.x); a3.y = fmaf(p3, dy, a3.y);
            a3.z = fmaf(p3, dz, a3.z); a3.w = fmaf(p3, dw, a3.w);
        }

        float* rw = red + w * (REP * DH);
        *(float4*)(rw + 0 * DH + lo) = a0;
        *(float4*)(rw + 1 * DH + lo) = a1;
        *(float4*)(rw + 2 * DH + lo) = a2;
        *(float4*)(rw + 3 * DH + lo) = a3;
    }
    __syncthreads();

    // ---- reduce 4 warps and write partial result ----
    {
        float* gout = g_part_acc + (size_t)mlbase * DH;
        #pragma unroll
        for (int o = tid; o < REP * DH; o += 128) {
            float s = 0.f;
            #pragma unroll
            for (int ww = 0; ww < 4; ++ww)
                s += red[ww * (REP * DH) + o];
            gout[o] = s;
        }
    }

    // ---- last-CTA-combines: log-sum-exp merge across chunks of this (b,g) ----
    __threadfence();                 // make partials visible before signaling
    if (tid == 0) {
        const int old = atomicAdd(&g_done[b * KHN + g], 1);
        s_last = (old == nc - 1);
    }
    __syncthreads();
    if (!s_last) return;
    __threadfence();                 // acquire: see all other CTAs' partials

    const int base = (b * KHN + g) * NCH;
    #pragma unroll
    for (int o = tid; o < REP * DH; o += 128) {
        const int r = o >> 7;        // rep head
        const int d = o & 127;       // dim

        // max over chunks (2 independent accumulators for MLP)
        float M0 = -INFINITY, M1 = -INFINITY;
        int cc = 0;
        for (; cc + 2 <= nc; cc += 2) {
            M0 = fmaxf(M0, g_part_ml[(base + cc) * REP + r].x);
            M1 = fmaxf(M1, g_part_ml[(base + cc + 1) * REP + r].x);
        }
        if (cc < nc) M0 = fmaxf(M0, g_part_ml[(base + cc) * REP + r].x);
        const float M = fmaxf(M0, M1);

        float L0 = 0.f, L1 = 0.f, A0 = 0.f, A1 = 0.f;
        cc = 0;
        for (; cc + 2 <= nc; cc += 2) {
            const float2 mla = g_part_ml[(base + cc) * REP + r];
            const float2 mlb = g_part_ml[(base + cc + 1) * REP + r];
            const float wa = __expf(mla.x - M);
            const float wb = __expf(mlb.x - M);
            const float va = g_part_acc[((size_t)(base + cc) * REP + r) * DH + d];
            const float vb = g_part_acc[((size_t)(base + cc + 1) * REP + r) * DH + d];
            L0 += mla.y * wa;  A0 = fmaf(wa, va, A0);
            L1 += mlb.y * wb;  A1 = fmaf(wb, vb, A1);
        }
        if (cc < nc) {
            const float2 ml = g_part_ml[(base + cc) * REP + r];
            const float wgt = __expf(ml.x - M);
            L0 += ml.y * wgt;
            A0 = fmaf(wgt, g_part_acc[((size_t)(base + cc) * REP + r) * DH + d], A0);
        }
        out[(size_t)b * HN * DH + (size_t)(g * REP + r) * DH + d] = (A0 + A1) / (L0 + L1);
    }

    if (tid == 0)
        g_done[b * KHN + g] = 0;     // reset for next call (deterministic state)
}

extern "C" void kernel_launch(void* const* d_in, const int* in_sizes, int n_in,
                              void* d_out, int out_size)
{
    const float* q  = (const float*)d_in[0];
    const float* k  = (const float*)d_in[1];
    const float* v  = (const float*)d_in[2];
    const float* kc = (const float*)d_in[3];
    const float* vc = (const float*)d_in[4];
    const int*   bt = (const int*)d_in[5];
    const int*   cl = (const int*)d_in[6];
    // d_in[7] = slot_mapping: unused — new token is substituted at position len-1
    float* out = (float*)d_out;

    // Single fused launch: split-KV partials (128-token chunks) + last-CTA combine.
    dim3 grid1(NCH, KHN, BN);       // chunk x kv_head x batch
    attn_partial_kernel<<<grid1, 128>>>(q, k, v, kc, vc, bt, cl, out);
}

// round 16
// speedup vs baseline: 1.1201x; 1.1201x over previous
#include <cuda_runtime.h>
#include <math.h>

#define NBLK 512
#define BS   256
#define KHN  8
#define DH   128
#define BN   32
#define HN   32
#define MBN  16
#define REP  4
#define QK_SCALE 0.08838834764831845f

// Split-KV partial results: per (b, kv_head, chunk, rep_head)
__device__ float  g_part_acc[BN * KHN * MBN * REP * DH];   // 8 MB
__device__ float2 g_part_ml [BN * KHN * MBN * REP];        // 128 KB
// Completion counters per (b, kv_head). Zero-initialized; the last CTA resets
// its counter to 0 after combining, so state is identical across replays.
__device__ int    g_done    [BN * KHN];

__global__ void __launch_bounds__(256, 5)
attn_partial_kernel(const float* __restrict__ q,
                    const float* __restrict__ knew,
                    const float* __restrict__ vnew,
                    const float* __restrict__ kc,
                    const float* __restrict__ vc,
                    const int*   __restrict__ bt,
                    const int*   __restrict__ cl,
                    float*       __restrict__ out)
{
    const int c = blockIdx.x;   // chunk (cache block index within sequence)
    const int g = blockIdx.y;   // kv head
    const int b = blockIdx.z;   // sequence

    const int len   = cl[b];
    const int start = c * BS;
    if (start >= len) return;                    // inactive chunk
    const int n    = min(BS, len - start);       // valid tokens in this chunk
    const int nc   = (len + BS - 1) >> 8;        // active chunks for this (b,g)
    const int last = len - 1;
    const int tsub = ((last >> 8) == c) ? (last & (BS - 1)) : -1;  // new-token slot
    const int blk  = bt[b * MBN + c];

    __shared__ float  qs[REP * DH];       // 2 KB: 4 query heads
    __shared__ float  sc[REP][BS];        // 4 KB: scores -> probabilities
    __shared__ float  red[8 * REP * DH];  // 16 KB: per-warp V partials
    __shared__ float2 ml_s[8][REP];       // 256 B: per-warp (m, l) per head
    __shared__ int    s_last;

    const int tid = threadIdx.x;

    // ---- load Q (heads g*4 .. g*4+3 are contiguous in q) ----
    {
        const size_t qoff = (size_t)b * HN * DH + (size_t)g * REP * DH;
        qs[tid]       = q[qoff + tid];
        qs[tid + 256] = q[qoff + tid + 256];
    }
    __syncthreads();

    const int w    = tid >> 5;
    const int lane = tid & 31;
    const int sub  = lane & 7;     // 8 lanes cooperate per token row
    const int grp  = lane >> 3;    // 4 tokens in flight per warp pass

    const size_t rowstride = (size_t)KHN * DH;   // floats between tokens
    const float* kbase = kc + ((size_t)blk * BS * KHN + (size_t)g) * DH;
    const float* knrow = knew + (size_t)(b * KHN + g) * DH;
    const float4* q4   = (const float4*)qs;

    // ========== WARP-INDEPENDENT MAIN BODY (no CTA barriers) ==========
    // Warp w owns tokens [32w, 32w+32): scores, warp-local softmax, V stream.

    // ---- K phase: scores for this warp's 32 tokens ----
    #pragma unroll 2
    for (int p = 0; p < 8; ++p) {
        const int t = w * 32 + p * 4 + grp;
        float s0 = 0.f, s1 = 0.f, s2 = 0.f, s3 = 0.f;
        if (t < n) {
            const float4* kr = (const float4*)((t == tsub)
                                 ? knrow
                                 : (kbase + (size_t)t * rowstride));
            #pragma unroll
            for (int j = 0; j < 4; ++j) {
                const float4 kv = kr[j * 8 + sub];
                float4 qa;
                qa = q4[      j * 8 + sub];
                s0 += kv.x*qa.x + kv.y*qa.y + kv.z*qa.z + kv.w*qa.w;
                qa = q4[32  + j * 8 + sub];
                s1 += kv.x*qa.x + kv.y*qa.y + kv.z*qa.z + kv.w*qa.w;
                qa = q4[64  + j * 8 + sub];
                s2 += kv.x*qa.x + kv.y*qa.y + kv.z*qa.z + kv.w*qa.w;
                qa = q4[96  + j * 8 + sub];
                s3 += kv.x*qa.x + kv.y*qa.y + kv.z*qa.z + kv.w*qa.w;
            }
        }
        #pragma unroll
        for (int m = 4; m > 0; m >>= 1) {
            s0 += __shfl_xor_sync(0xffffffffu, s0, m);
            s1 += __shfl_xor_sync(0xffffffffu, s1, m);
            s2 += __shfl_xor_sync(0xffffffffu, s2, m);
            s3 += __shfl_xor_sync(0xffffffffu, s3, m);
        }
        if (sub < 4) {
            const float val = (sub == 0) ? s0 : (sub == 1) ? s1 : (sub == 2) ? s2 : s3;
            sc[sub][t] = (t < n) ? val * QK_SCALE : -INFINITY;
        }
    }
    __syncwarp();

    // ---- warp-local softmax over this warp's 32 tokens (4 heads) ----
    {
        const int t = w * 32 + lane;
        float v0 = sc[0][t], v1 = sc[1][t], v2 = sc[2][t], v3 = sc[3][t];
        float m0 = v0, m1 = v1, m2 = v2, m3 = v3;
        #pragma unroll
        for (int s = 16; s > 0; s >>= 1) {
            m0 = fmaxf(m0, __shfl_xor_sync(0xffffffffu, m0, s));
            m1 = fmaxf(m1, __shfl_xor_sync(0xffffffffu, m1, s));
            m2 = fmaxf(m2, __shfl_xor_sync(0xffffffffu, m2, s));
            m3 = fmaxf(m3, __shfl_xor_sync(0xffffffffu, m3, s));
        }
        // empty warp (all -inf): clamp so exp gives 0, not NaN
        const float c0 = (m0 == -INFINITY) ? 0.f : m0;
        const float c1 = (m1 == -INFINITY) ? 0.f : m1;
        const float c2 = (m2 == -INFINITY) ? 0.f : m2;
        const float c3 = (m3 == -INFINITY) ? 0.f : m3;
        float e0 = __expf(v0 - c0), e1 = __expf(v1 - c1);
        float e2 = __expf(v2 - c2), e3 = __expf(v3 - c3);
        sc[0][t] = e0;  sc[1][t] = e1;  sc[2][t] = e2;  sc[3][t] = e3;
        float l0 = e0, l1 = e1, l2 = e2, l3 = e3;
        #pragma unroll
        for (int s = 16; s > 0; s >>= 1) {
            l0 += __shfl_xor_sync(0xffffffffu, l0, s);
            l1 += __shfl_xor_sync(0xffffffffu, l1, s);
            l2 += __shfl_xor_sync(0xffffffffu, l2, s);
            l3 += __shfl_xor_sync(0xffffffffu, l3, s);
        }
        if (lane == 0) {
            ml_s[w][0] = make_float2(m0, l0);
            ml_s[w][1] = make_float2(m1, l1);
            ml_s[w][2] = make_float2(m2, l2);
            ml_s[w][3] = make_float2(m3, l3);
        }
        __syncwarp();
    }

    // ---- V phase: accumulate this warp's 32 tokens (lane owns float4 dims) ----
    {
        const int lo = lane * 4;
        const float* vrow0 = vc + ((size_t)blk * BS * KHN + (size_t)g) * DH + lo;

        float4 a0 = make_float4(0.f, 0.f, 0.f, 0.f);
        float4 a1 = a0, a2 = a0, a3 = a0;

        const int t0   = w * 32;
        const int tend = min(t0 + 32, n);
        #pragma unroll 4
        for (int t = t0; t < tend; ++t) {
            const float4 vv = *(const float4*)(vrow0 + (size_t)t * rowstride);
            const float p0 = sc[0][t];
            const float p1 = sc[1][t];
            const float p2 = sc[2][t];
            const float p3 = sc[3][t];
            a0.x = fmaf(p0, vv.x, a0.x); a0.y = fmaf(p0, vv.y, a0.y);
            a0.z = fmaf(p0, vv.z, a0.z); a0.w = fmaf(p0, vv.w, a0.w);
            a1.x = fmaf(p1, vv.x, a1.x); a1.y = fmaf(p1, vv.y, a1.y);
            a1.z = fmaf(p1, vv.z, a1.z); a1.w = fmaf(p1, vv.w, a1.w);
            a2.x = fmaf(p2, vv.x, a2.x); a2.y = fmaf(p2, vv.y, a2.y);
            a2.z = fmaf(p2, vv.z, a2.z); a2.w = fmaf(p2, vv.w, a2.w);
            a3.x = fmaf(p3, vv.x, a3.x); a3.y = fmaf(p3, vv.y, a3.y);
            a3.z = fmaf(p3, vv.z, a3.z); a3.w = fmaf(p3, vv.w, a3.w);
        }

        // new-token fix-up: acc += p[tsub] * (v_new - v_stale)
        if (tsub >= t0 && tsub < tend) {
            const float4 vst = *(const float4*)(vrow0 + (size_t)tsub * rowstride);
            const float4 vn4 = *(const float4*)(vnew + (size_t)(b * KHN + g) * DH + lo);
            const float dx = vn4.x - vst.x, dy = vn4.y - vst.y;
            const float dz = vn4.z - vst.z, dw = vn4.w - vst.w;
            const float p0 = sc[0][tsub], p1 = sc[1][tsub];
            const float p2 = sc[2][tsub], p3 = sc[3][tsub];
            a0.x = fmaf(p0, dx, a0.x); a0.y = fmaf(p0, dy, a0.y);
            a0.z = fmaf(p0, dz, a0.z); a0.w = fmaf(p0, dw, a0.w);
            a1.x = fmaf(p1, dx, a1.x); a1.y = fmaf(p1, dy, a1.y);
            a1.z = fmaf(p1, dz, a1.z); a1.w = fmaf(p1, dw, a1.w);
            a2.x = fmaf(p2, dx, a2.x); a2.y = fmaf(p2, dy, a2.y);
            a2.z = fmaf(p2, dz, a2.z); a2.w = fmaf(p2, dw, a2.w);
            a3.x = fmaf(p3, dx, a3.x); a3.y = fmaf(p3, dy, a3.y);
            a3.z = fmaf(p3, dz, a3.z); a3.w = fmaf(p3, dw, a3.w);
        }

        float* rw = red + w * (REP * DH);
        *(float4*)(rw + 0 * DH + lo) = a0;
        *(float4*)(rw + 1 * DH + lo) = a1;
        *(float4*)(rw + 2 * DH + lo) = a2;
        *(float4*)(rw + 3 * DH + lo) = a3;
    }
    __syncthreads();   // the ONLY cta barrier after Q load

    // ---- cross-warp log-sum-exp merge -> chunk partial ----
    const int mlbase = ((b * KHN + g) * MBN + c) * REP;
    #pragma unroll
    for (int o = tid; o < REP * DH; o += 256) {
        const int r = o >> 7;

        float M = -INFINITY;
        #pragma unroll
        for (int ww = 0; ww < 8; ++ww)
            M = fmaxf(M, ml_s[ww][r].x);

        float L = 0.f, A = 0.f;
        #pragma unroll
        for (int ww = 0; ww < 8; ++ww) {
            const float2 ml = ml_s[ww][r];
            const float wt = __expf(ml.x - M);   // m=-inf -> 0
            L += ml.y * wt;
            A = fmaf(wt, red[ww * (REP * DH) + o], A);
        }
        g_part_acc[(size_t)mlbase * DH + o] = A;
        if ((o & 127) == 0)
            g_part_ml[mlbase + r] = make_float2(M, L);
    }

    // ---- last-CTA-combines: log-sum-exp merge across chunks of this (b,g) ----
    __threadfence();                 // make partials visible before signaling
    if (tid == 0) {
        const int old = atomicAdd(&g_done[b * KHN + g], 1);
        s_last = (old == nc - 1);
    }
    __syncthreads();
    if (!s_last) return;
    __threadfence();                 // acquire: see all other CTAs' partials

    const int base = (b * KHN + g) * MBN;
    #pragma unroll
    for (int o = tid; o < REP * DH; o += 256) {
        const int r = o >> 7;        // rep head
        const int d = o & 127;       // dim

        float M = -INFINITY;
        for (int cc = 0; cc < nc; ++cc)
            M = fmaxf(M, g_part_ml[(base + cc) * REP + r].x);

        float L = 0.f, acc = 0.f;
        for (int cc = 0; cc < nc; ++cc) {
            const float2 ml = g_part_ml[(base + cc) * REP + r];
            const float wgt = __expf(ml.x - M);
            L += ml.y * wgt;
            acc = fmaf(wgt, g_part_acc[((size_t)(base + cc) * REP + r) * DH + d], acc);
        }
        out[(size_t)b * HN * DH + (size_t)(g * REP + r) * DH + d] = acc / L;
    }

    if (tid == 0)
        g_done[b * KHN + g] = 0;     // reset for next call (deterministic state)
}

extern "C" void kernel_launch(void* const* d_in, const int* in_sizes, int n_in,
                              void* d_out, int out_size)
{
    const float* q  = (const float*)d_in[0];
    const float* k  = (const float*)d_in[1];
    const float* v  = (const float*)d_in[2];
    const float* kc = (const float*)d_in[3];
    const float* vc = (const float*)d_in[4];
    const int*   bt = (const int*)d_in[5];
    const int*   cl = (const int*)d_in[6];
    // d_in[7] = slot_mapping: unused — new token is substituted at position len-1
    float* out = (float*)d_out;

    // Single fused launch: warp-independent split-KV partials + last-CTA combine.
    dim3 grid1(MBN, KHN, BN);       // chunk x kv_head x batch
    attn_partial_kernel<<<grid1, 256>>>(q, k, v, kc, vc, bt, cl, out);
}

// round 17
// speedup vs baseline: 1.2195x; 1.0888x over previous
#include <cuda_runtime.h>
#include <math.h>

#define NBLK 512
#define BS   256
#define KHN  8
#define DH   128
#define BN   32
#define HN   32
#define MBN  16
#define REP  4
#define QK_SCALE 0.08838834764831845f

// Split-KV partial results: per (b, kv_head, chunk, rep_head)
__device__ float  g_part_acc[BN * KHN * MBN * REP * DH];   // 8 MB
__device__ float2 g_part_ml [BN * KHN * MBN * REP];        // 128 KB
// Completion counters per (b, kv_head). Zero-initialized; the last CTA resets
// its counter to 0 after combining, so state is identical across replays.
__device__ int    g_done    [BN * KHN];

__global__ void __launch_bounds__(256, 5)
attn_partial_kernel(const float* __restrict__ q,
                    const float* __restrict__ knew,
                    const float* __restrict__ vnew,
                    const float* __restrict__ kc,
                    const float* __restrict__ vc,
                    const int*   __restrict__ bt,
                    const int*   __restrict__ cl,
                    float*       __restrict__ out)
{
    const int c = blockIdx.x;   // chunk (cache block index within sequence)
    const int g = blockIdx.y;   // kv head
    const int b = blockIdx.z;   // sequence

    const int len   = cl[b];
    const int start = c * BS;
    if (start >= len) return;                    // inactive chunk
    const int n    = min(BS, len - start);       // valid tokens in this chunk
    const int nc   = (len + BS - 1) >> 8;        // active chunks for this (b,g)
    const int last = len - 1;
    const int tsub = ((last >> 8) == c) ? (last & (BS - 1)) : -1;  // new-token slot
    const int blk  = bt[b * MBN + c];

    __shared__ float qs[REP * DH];          // 2 KB: 4 query heads
    __shared__ float sc[BS][REP];           // 4 KB: AoS scores -> probabilities
    __shared__ float red[8 * REP * DH];     // 16 KB: per-warp V partials
    __shared__ int   s_last;

    const int tid = threadIdx.x;

    // ---- load Q (heads g*4 .. g*4+3 are contiguous in q) ----
    {
        const size_t qoff = (size_t)b * HN * DH + (size_t)g * REP * DH;
        qs[tid]       = q[qoff + tid];
        qs[tid + 256] = q[qoff + tid + 256];
    }
    __syncthreads();

    const int w    = tid >> 5;
    const int lane = tid & 31;
    const int sub  = lane & 7;     // 8 lanes cooperate per token row
    const int grp  = lane >> 3;    // 4 tokens in flight per warp pass

    const size_t rowstride = (size_t)KHN * DH;   // floats between tokens
    const float* kbase = kc + ((size_t)blk * BS * KHN + (size_t)g) * DH;
    const float* knrow = knew + (size_t)(b * KHN + g) * DH;
    const float4* q4   = (const float4*)qs;

    // ---- phase 1: scores = (Q . K) * scale ----
    // Lane group of 8 reads CONTIGUOUS 128B per j-step: kr[j*8 + sub].
    // K is zero-reuse -> streaming loads (__ldcs).
    #pragma unroll 2
    for (int p = 0; p < 8; ++p) {
        const int t = w * 32 + p * 4 + grp;       // 0..255, all covered
        float s0 = 0.f, s1 = 0.f, s2 = 0.f, s3 = 0.f;
        if (t < n) {
            const float4* kr = (const float4*)((t == tsub)
                                 ? knrow
                                 : (kbase + (size_t)t * rowstride));
            #pragma unroll
            for (int j = 0; j < 4; ++j) {
                const float4 kv = __ldcs(kr + j * 8 + sub);
                float4 qa;
                qa = q4[      j * 8 + sub];
                s0 += kv.x*qa.x + kv.y*qa.y + kv.z*qa.z + kv.w*qa.w;
                qa = q4[32  + j * 8 + sub];
                s1 += kv.x*qa.x + kv.y*qa.y + kv.z*qa.z + kv.w*qa.w;
                qa = q4[64  + j * 8 + sub];
                s2 += kv.x*qa.x + kv.y*qa.y + kv.z*qa.z + kv.w*qa.w;
                qa = q4[96  + j * 8 + sub];
                s3 += kv.x*qa.x + kv.y*qa.y + kv.z*qa.z + kv.w*qa.w;
            }
        }
        #pragma unroll
        for (int m = 4; m > 0; m >>= 1) {
            s0 += __shfl_xor_sync(0xffffffffu, s0, m);
            s1 += __shfl_xor_sync(0xffffffffu, s1, m);
            s2 += __shfl_xor_sync(0xffffffffu, s2, m);
            s3 += __shfl_xor_sync(0xffffffffu, s3, m);
        }
        if (sub < 4) {
            const float val = (sub == 0) ? s0 : (sub == 1) ? s1 : (sub == 2) ? s2 : s3;
            sc[t][sub] = (t < n) ? val * QK_SCALE : -INFINITY;
        }
    }
    __syncthreads();

    // ---- phase 2: per-head chunk softmax (unnormalized), warp r handles head r ----
    const int mlbase = ((b * KHN + g) * MBN + c) * REP;
    if (w < 4) {
        float vv[8];
        float m = -INFINITY;
        #pragma unroll
        for (int j = 0; j < 8; ++j) {
            vv[j] = sc[lane + 32 * j][w];
            m = fmaxf(m, vv[j]);
        }
        #pragma unroll
        for (int s = 16; s > 0; s >>= 1)
            m = fmaxf(m, __shfl_xor_sync(0xffffffffu, m, s));
        float l = 0.f;
        #pragma unroll
        for (int j = 0; j < 8; ++j) {
            const float e = __expf(vv[j] - m);   // exp(-inf)=0 for masked slots
            l += e;
            sc[lane + 32 * j][w] = e;
        }
        #pragma unroll
        for (int s = 16; s > 0; s >>= 1)
            l += __shfl_xor_sync(0xffffffffu, l, s);
        if (lane == 0)
            g_part_ml[mlbase + w] = make_float2(m, l);
    }
    __syncthreads();

    // ---- phase 3: acc = P . V  (warp per token row; lane owns float4 of dims) ----
    // AoS probabilities: ONE LDS.128 broadcast per token instead of 4 LDS.32.
    // V read from cache for every token; new-token fix-up after the loop:
    //   acc += p[tsub] * (v_new - v_stale).  Stale cache values are finite.
    {
        const int lo = lane * 4;   // float offset within the 128-dim row
        const float* vrow0 = vc + ((size_t)blk * BS * KHN + (size_t)g) * DH + lo;

        float4 a0 = make_float4(0.f, 0.f, 0.f, 0.f);
        float4 a1 = a0, a2 = a0, a3 = a0;

        #pragma unroll 4
        for (int t = w; t < n; t += 8) {
            const float4 vv = __ldcs((const float4*)(vrow0 + (size_t)t * rowstride));
            const float4 pv = *(const float4*)&sc[t][0];
            a0.x = fmaf(pv.x, vv.x, a0.x); a0.y = fmaf(pv.x, vv.y, a0.y);
            a0.z = fmaf(pv.x, vv.z, a0.z); a0.w = fmaf(pv.x, vv.w, a0.w);
            a1.x = fmaf(pv.y, vv.x, a1.x); a1.y = fmaf(pv.y, vv.y, a1.y);
            a1.z = fmaf(pv.y, vv.z, a1.z); a1.w = fmaf(pv.y, vv.w, a1.w);
            a2.x = fmaf(pv.z, vv.x, a2.x); a2.y = fmaf(pv.z, vv.y, a2.y);
            a2.z = fmaf(pv.z, vv.z, a2.z); a2.w = fmaf(pv.z, vv.w, a2.w);
            a3.x = fmaf(pv.w, vv.x, a3.x); a3.y = fmaf(pv.w, vv.y, a3.y);
            a3.z = fmaf(pv.w, vv.z, a3.z); a3.w = fmaf(pv.w, vv.w, a3.w);
        }

        if (tsub >= 0 && (tsub & 7) == w) {
            const float4 vst = *(const float4*)(vrow0 + (size_t)tsub * rowstride);
            const float4 vn4 = *(const float4*)(vnew + (size_t)(b * KHN + g) * DH + lo);
            const float dx = vn4.x - vst.x, dy = vn4.y - vst.y;
            const float dz = vn4.z - vst.z, dw = vn4.w - vst.w;
            const float4 pv = *(const float4*)&sc[tsub][0];
            a0.x = fmaf(pv.x, dx, a0.x); a0.y = fmaf(pv.x, dy, a0.y);
            a0.z = fmaf(pv.x, dz, a0.z); a0.w = fmaf(pv.x, dw, a0.w);
            a1.x = fmaf(pv.y, dx, a1.x); a1.y = fmaf(pv.y, dy, a1.y);
            a1.z = fmaf(pv.y, dz, a1.z); a1.w = fmaf(pv.y, dw, a1.w);
            a2.x = fmaf(pv.z, dx, a2.x); a2.y = fmaf(pv.z, dy, a2.y);
            a2.z = fmaf(pv.z, dz, a2.z); a2.w = fmaf(pv.z, dw, a2.w);
            a3.x = fmaf(pv.w, dx, a3.x); a3.y = fmaf(pv.w, dy, a3.y);
            a3.z = fmaf(pv.w, dz, a3.z); a3.w = fmaf(pv.w, dw, a3.w);
        }

        float* rw = red + w * (REP * DH);
        *(float4*)(rw + 0 * DH + lo) = a0;
        *(float4*)(rw + 1 * DH + lo) = a1;
        *(float4*)(rw + 2 * DH + lo) = a2;
        *(float4*)(rw + 3 * DH + lo) = a3;
    }
    __syncthreads();

    // ---- reduce 8 warps and write partial result ----
    {
        float* gout = g_part_acc + (size_t)mlbase * DH;
        #pragma unroll
        for (int o = tid; o < REP * DH; o += 256) {
            float s = 0.f;
            #pragma unroll
            for (int ww = 0; ww < 8; ++ww)
                s += red[ww * (REP * DH) + o];
            gout[o] = s;
        }
    }

    // ---- last-CTA-combines: log-sum-exp merge across chunks of this (b,g) ----
    __threadfence();                 // make partials visible before signaling
    if (tid == 0) {
        const int old = atomicAdd(&g_done[b * KHN + g], 1);
        s_last = (old == nc - 1);
    }
    __syncthreads();
    if (!s_last) return;
    __threadfence();                 // acquire: see all other CTAs' partials

    const int base = (b * KHN + g) * MBN;
    #pragma unroll
    for (int o = tid; o < REP * DH; o += 256) {
        const int r = o >> 7;        // rep head
        const int d = o & 127;       // dim

        float M = -INFINITY;
        for (int cc = 0; cc < nc; ++cc)
            M = fmaxf(M, g_part_ml[(base + cc) * REP + r].x);

        float L = 0.f, acc = 0.f;
        for (int cc = 0; cc < nc; ++cc) {
            const float2 ml = g_part_ml[(base + cc) * REP + r];
            const float wgt = __expf(ml.x - M);
            L += ml.y * wgt;
            acc = fmaf(wgt, g_part_acc[((size_t)(base + cc) * REP + r) * DH + d], acc);
        }
        out[(size_t)b * HN * DH + (size_t)(g * REP + r) * DH + d] = acc / L;
    }

    if (tid == 0)
        g_done[b * KHN + g] = 0;     // reset for next call (deterministic state)
}

extern "C" void kernel_launch(void* const* d_in, const int* in_sizes, int n_in,
                              void* d_out, int out_size)
{
    const float* q  = (const float*)d_in[0];
    const float* k  = (const float*)d_in[1];
    const float* v  = (const float*)d_in[2];
    const float* kc = (const float*)d_in[3];
    const float* vc = (const float*)d_in[4];
    const int*   bt = (const int*)d_in[5];
    const int*   cl = (const int*)d_in[6];
    // d_in[7] = slot_mapping: unused — new token is substituted at position len-1
    float* out = (float*)d_out;

    // Single fused launch: split-KV partials + last-CTA combine.
    dim3 grid1(MBN, KHN, BN);       // chunk x kv_head x batch
    attn_partial_kernel<<<grid1, 256>>>(q, k, v, kc, vc, bt, cl, out);
}